// round 5
// baseline (speedup 1.0000x reference)
#include <cuda_runtime.h>

#define HH 256
#define WW 512
#define CC 32
#define BB 2
#define HL (HH/4)
#define WL (WW/4)
#define HWs ((size_t)HH*WW)

typedef unsigned long long u64;

#define FMA2(d,a,b,c) asm("fma.rn.f32x2 %0,%1,%2,%3;" : "=l"(d) : "l"(a), "l"(b), "l"(c))
#define ADD2(d,a,b)   asm("add.rn.f32x2 %0,%1,%2;"    : "=l"(d) : "l"(a), "l"(b))
#define MUL2(d,a,b)   asm("mul.rn.f32x2 %0,%1,%2;"    : "=l"(d) : "l"(a), "l"(b))
#define PACK2(d,lo,hi) asm("mov.b64 %0,{%1,%2};" : "=l"(d) : "r"(__float_as_uint(lo)), "r"(__float_as_uint(hi)))
#define UNPK2(lo,hi,s) do { unsigned _ul,_uh; \
    asm("mov.b64 {%0,%1},%2;" : "=r"(_ul), "=r"(_uh) : "l"(s)); \
    (lo)=__uint_as_float(_ul); (hi)=__uint_as_float(_uh); } while(0)

// tail for one direction, both pixels: lrelu(h1) -> layer2 -> lrelu -> layer3 -> logits
__device__ __forceinline__ void dir_tail(
    const u64* accA, const u64* accB,
    const float* __restrict__ s_w2T, const float* __restrict__ w3r,
    bool validA, bool validB, float* slotA, float* slotB, u64 c001)
{
    u64 g1A[16], g1B[16];
#pragma unroll
    for (int o = 0; o < 8; ++o) {
        u64 mA, mB; float x0,x1,m0,m1,y0,y1,n0,n1;
        MUL2(mA, accA[o], c001);
        MUL2(mB, accB[o], c001);
        UNPK2(x0,x1,accA[o]); UNPK2(m0,m1,mA);
        UNPK2(y0,y1,accB[o]); UNPK2(n0,n1,mB);
        x0 = fmaxf(x0,m0); x1 = fmaxf(x1,m1);
        y0 = fmaxf(y0,n0); y1 = fmaxf(y1,n1);
        PACK2(g1A[o*2+0],x0,x0); PACK2(g1A[o*2+1],x1,x1);
        PACK2(g1B[o*2+0],y0,y0); PACK2(g1B[o*2+1],y1,y1);
    }
    u64 c2A[4], c2B[4];
#pragma unroll
    for (int o = 0; o < 4; ++o) { c2A[o] = 0ull; c2B[o] = 0ull; }
#pragma unroll
    for (int k = 0; k < 16; ++k) {
        const ulonglong2* wr = (const ulonglong2*)&s_w2T[k*8];
        ulonglong2 q0 = wr[0], q1 = wr[1];
        FMA2(c2A[0], q0.x, g1A[k], c2A[0]);
        FMA2(c2A[1], q0.y, g1A[k], c2A[1]);
        FMA2(c2A[2], q1.x, g1A[k], c2A[2]);
        FMA2(c2A[3], q1.y, g1A[k], c2A[3]);
        FMA2(c2B[0], q0.x, g1B[k], c2B[0]);
        FMA2(c2B[1], q0.y, g1B[k], c2B[1]);
        FMA2(c2B[2], q1.x, g1B[k], c2B[2]);
        FMA2(c2B[3], q1.y, g1B[k], c2B[3]);
    }
    float aA = 0.f, aB = 0.f;
#pragma unroll
    for (int o = 0; o < 4; ++o) {
        u64 mA, mB; float x0,x1,m0,m1,y0,y1,n0,n1;
        MUL2(mA, c2A[o], c001);
        MUL2(mB, c2B[o], c001);
        UNPK2(x0,x1,c2A[o]); UNPK2(m0,m1,mA);
        UNPK2(y0,y1,c2B[o]); UNPK2(n0,n1,mB);
        x0 = fmaxf(x0,m0); x1 = fmaxf(x1,m1);
        y0 = fmaxf(y0,n0); y1 = fmaxf(y1,n1);
        aA = fmaf(w3r[o*2+0], x0, aA);
        aA = fmaf(w3r[o*2+1], x1, aA);
        aB = fmaf(w3r[o*2+0], y0, aB);
        aB = fmaf(w3r[o*2+1], y1, aB);
    }
    *slotA = validA ? aA : -100.0f;
    *slotB = validB ? aB : -100.0f;
}

// Tile: 64 wide x 8 tall. 256 threads; thread owns pixels (h,w) and (h,w+32).
// LR blocks: 16 wide x 2 tall; neighborhood 18 x 4.
__global__ void __launch_bounds__(256, 1)
erc_kernel(const float* __restrict__ lr, const float* __restrict__ hr,
           const float* __restrict__ w0, const float* __restrict__ w1,
           const float* __restrict__ w2, const float* __restrict__ w3,
           float* __restrict__ out)
{
    __shared__ __align__(16) float s_w0T[66*32];     // [k][o]
    __shared__ __align__(16) float s_w1T[32*16];     // [k][o]
    __shared__ __align__(16) float s_w2T[16*8];      // [k][o]
    __shared__ __align__(16) float s_w3[8];
    __shared__ __align__(16) float s_lrvec[72*32];   // [j*18+i][c]
    __shared__ __align__(16) float s_lrproj[72*36];  // [j*18+i][o], pad->36
    __shared__ float s_logit[512*9];                 // [pix*9+d]

    const int tid = threadIdx.x;
    const int b  = blockIdx.z;
    const int tx = tid & 31, ty = tid >> 5;
    const int h  = blockIdx.y * 8 + ty;
    const int wA = blockIdx.x * 64 + tx;
    const int wB = wA + 32;

    // ---------------- Phase A: stage weights + lr vectors ----------------
    for (int idx = tid; idx < 66*32; idx += 256) {
        int k = idx >> 5, o = idx & 31;
        s_w0T[idx] = w0[o*66 + k];
    }
    for (int idx = tid; idx < 32*16; idx += 256) {
        int k = idx >> 4, o = idx & 15;
        s_w1T[idx] = w1[o*32 + k];
    }
    if (tid < 16*8) { int k = tid >> 3, o = tid & 7; s_w2T[tid] = w2[o*16 + k]; }
    if (tid < 8)    s_w3[tid] = w3[tid];
    {
        const int y0 = blockIdx.y * 2 - 1;
        const int x0 = blockIdx.x * 16 - 1;
        for (int idx = tid; idx < 72*32; idx += 256) {
            int c = idx & 31, pos = idx >> 5;
            int j = pos / 18, i = pos - j*18;
            int yy = min(max(y0 + j, 0), HL - 1);   // clamped loads only feed masked dirs
            int xx = min(max(x0 + i, 0), WL - 1);
            s_lrvec[idx] = lr[(((size_t)b*CC + c)*HL + yy)*WL + xx];
        }
    }
    __syncthreads();

    // ------- Phase B: lr projections (W0_lr @ lrvec) -------
    for (int idx = tid; idx < 72*32; idx += 256) {
        int o = idx & 31, pos = idx >> 5;
        const float4* v4 = (const float4*)&s_lrvec[pos*32];
        float acc = 0.f;
#pragma unroll
        for (int c4 = 0; c4 < 8; ++c4) {
            float4 v = v4[c4];
            acc = fmaf(v.x, s_w0T[(c4*4+0)*32 + o], acc);
            acc = fmaf(v.y, s_w0T[(c4*4+1)*32 + o], acc);
            acc = fmaf(v.z, s_w0T[(c4*4+2)*32 + o], acc);
            acc = fmaf(v.w, s_w0T[(c4*4+3)*32 + o], acc);
        }
        s_lrproj[pos*36 + o] = acc;
    }
    __syncthreads();

    // ---------------- hrproj (packed o-pairs, both pixels) ----------------
    u64 hrpA[16], hrpB[16];
#pragma unroll
    for (int j = 0; j < 16; ++j) { hrpA[j] = 0ull; hrpB[j] = 0ull; }
    {
        const float* p = hr + (size_t)b*CC*HWs + (size_t)h*WW + wA;
#pragma unroll
        for (int ct = 0; ct < 4; ++ct) {
            float fA[8], fB[8];
#pragma unroll
            for (int j = 0; j < 8; ++j) {
                fA[j] = p[(size_t)(ct*8+j)*HWs];
                fB[j] = p[(size_t)(ct*8+j)*HWs + 32];
            }
#pragma unroll
            for (int j = 0; j < 8; ++j) {
                u64 vA2, vB2;
                PACK2(vA2, fA[j], fA[j]);
                PACK2(vB2, fB[j], fB[j]);
                const ulonglong2* wr = (const ulonglong2*)&s_w0T[(32 + ct*8 + j)*32];
#pragma unroll
                for (int q = 0; q < 8; ++q) {
                    ulonglong2 ww = wr[q];
                    FMA2(hrpA[q*2+0], ww.x, vA2, hrpA[q*2+0]);
                    FMA2(hrpA[q*2+1], ww.y, vA2, hrpA[q*2+1]);
                    FMA2(hrpB[q*2+0], ww.x, vB2, hrpB[q*2+0]);
                    FMA2(hrpB[q*2+1], ww.y, vB2, hrpB[q*2+1]);
                }
            }
        }
    }

    const int px = wA & 3, py = h & 3;   // wB has same parity (32 % 4 == 0)
    const int byl = ty >> 2;
    const int bxlA = tx >> 2;
    const float fxa0 = (float)((px < 2) ? px - 2 : px - 1);
    const float fxa1 = (float)(4 - px);
    const float fxa2 = (float)(px + 1);
    const float fyb0 = (float)((py < 2) ? py - 2 : py - 1);
    const float fyb1 = (float)(4 - py);
    const float fyb2 = (float)(py + 1);
    // direction order: c, l, r, t, b, lt, rt, lb, rb
    const unsigned CA  = (0u<<0)|(1u<<2)|(2u<<4)|(0u<<6)|(0u<<8)|(1u<<10)|(2u<<12)|(0u<<14)|(0u<<16);
    const unsigned CB  = (0u<<0)|(0u<<2)|(0u<<4)|(1u<<6)|(2u<<8)|(0u<<10)|(0u<<12)|(1u<<14)|(2u<<16);
    const unsigned DY1 = (1u<<0)|(1u<<2)|(1u<<4)|(0u<<6)|(2u<<8)|(0u<<10)|(0u<<12)|(2u<<14)|(2u<<16);
    const unsigned DX1 = (1u<<0)|(0u<<2)|(2u<<4)|(1u<<6)|(1u<<8)|(0u<<10)|(2u<<12)|(0u<<14)|(2u<<16);

    float w3r[8];
#pragma unroll
    for (int j = 0; j < 8; ++j) w3r[j] = s_w3[j];
    u64 c001;
    PACK2(c001, 0.01f, 0.01f);

    const float* wap = &s_w0T[64*32];
    const float* wbp = &s_w0T[65*32];

    // ============ direction pairs: (0,1),(2,3),(4,5),(6,7) ============
#pragma unroll 1
    for (int pb = 0; pb < 4; ++pb) {
        const int d0 = pb*2, d1 = d0 + 1;

        const float* lp[4];   // stream: 0=d0/pixA 1=d0/pixB 2=d1/pixA 3=d1/pixB
        u64 dA2[4], dB2[4];
        bool vld[4];
#pragma unroll
        for (int e = 0; e < 2; ++e) {
            const int d = (e == 0) ? d0 : d1;
            const int dy1 = (DY1 >> (2*d)) & 3;
            const int dx1 = (DX1 >> (2*d)) & 3;
            bool vA = true, vB = true;
            if (dx1 == 0) { vA = vA && (wA >= 4);     vB = vB && (wB >= 4); }
            if (dx1 == 2) { vA = vA && (wA < WW - 4); vB = vB && (wB < WW - 4); }
            if (dy1 == 0) { vA = vA && (h >= 4);      vB = vB && (h >= 4); }
            if (dy1 == 2) { vA = vA && (h < HH - 4);  vB = vB && (h < HH - 4); }
            const int ca = (CA >> (2*d)) & 3, cb = (CB >> (2*d)) & 3;
            const float dAv = (ca == 0) ? fxa0 : ((ca == 1) ? fxa1 : fxa2);
            const float dBv = (cb == 0) ? fyb0 : ((cb == 1) ? fyb1 : fyb2);
            u64 a2, b2;
            PACK2(a2, dAv, dAv);
            PACK2(b2, dBv, dBv);
            const int row = (byl + dy1)*18 + (bxlA + dx1);
            lp[e*2+0] = &s_lrproj[row*36];
            lp[e*2+1] = &s_lrproj[(row + 8)*36];
            dA2[e*2+0] = a2; dA2[e*2+1] = a2;
            dB2[e*2+0] = b2; dB2[e*2+1] = b2;
            vld[e*2+0] = vA; vld[e*2+1] = vB;
        }

        u64 acc[4][8];
#pragma unroll
        for (int s = 0; s < 4; ++s)
#pragma unroll
            for (int o = 0; o < 8; ++o) acc[s][o] = 0ull;

#pragma unroll
        for (int q = 0; q < 16; ++q) {
            const u64 wa2 = *(const u64*)&wap[q*2];
            const u64 wb2 = *(const u64*)&wbp[q*2];
            u64 h0[4], h1v[4];
#pragma unroll
            for (int s = 0; s < 4; ++s) {
                const u64 l2 = *(const u64*)(lp[s] + q*2);
                u64 v;
                ADD2(v, ((s & 1) ? hrpB[q] : hrpA[q]), l2);
                FMA2(v, dA2[s], wa2, v);
                FMA2(v, dB2[s], wb2, v);
                u64 m; float x0,x1,m0,m1;
                MUL2(m, v, c001);
                UNPK2(x0,x1,v); UNPK2(m0,m1,m);
                x0 = fmaxf(x0,m0); x1 = fmaxf(x1,m1);
                PACK2(h0[s],  x0, x0);
                PACK2(h1v[s], x1, x1);
            }
            {   // channel 2q
                const ulonglong2* wr = (const ulonglong2*)&s_w1T[(2*q)*16];
                ulonglong2 r0 = wr[0], r1 = wr[1], r2 = wr[2], r3 = wr[3];
#pragma unroll
                for (int s = 0; s < 4; ++s) {
                    FMA2(acc[s][0], r0.x, h0[s], acc[s][0]);
                    FMA2(acc[s][1], r0.y, h0[s], acc[s][1]);
                    FMA2(acc[s][2], r1.x, h0[s], acc[s][2]);
                    FMA2(acc[s][3], r1.y, h0[s], acc[s][3]);
                    FMA2(acc[s][4], r2.x, h0[s], acc[s][4]);
                    FMA2(acc[s][5], r2.y, h0[s], acc[s][5]);
                    FMA2(acc[s][6], r3.x, h0[s], acc[s][6]);
                    FMA2(acc[s][7], r3.y, h0[s], acc[s][7]);
                }
            }
            {   // channel 2q+1
                const ulonglong2* wr = (const ulonglong2*)&s_w1T[(2*q+1)*16];
                ulonglong2 r0 = wr[0], r1 = wr[1], r2 = wr[2], r3 = wr[3];
#pragma unroll
                for (int s = 0; s < 4; ++s) {
                    FMA2(acc[s][0], r0.x, h1v[s], acc[s][0]);
                    FMA2(acc[s][1], r0.y, h1v[s], acc[s][1]);
                    FMA2(acc[s][2], r1.x, h1v[s], acc[s][2]);
                    FMA2(acc[s][3], r1.y, h1v[s], acc[s][3]);
                    FMA2(acc[s][4], r2.x, h1v[s], acc[s][4]);
                    FMA2(acc[s][5], r2.y, h1v[s], acc[s][5]);
                    FMA2(acc[s][6], r3.x, h1v[s], acc[s][6]);
                    FMA2(acc[s][7], r3.y, h1v[s], acc[s][7]);
                }
            }
        }

        dir_tail(acc[0], acc[1], s_w2T, w3r, vld[0], vld[1],
                 &s_logit[tid*9 + d0], &s_logit[(tid+256)*9 + d0], c001);
        dir_tail(acc[2], acc[3], s_w2T, w3r, vld[2], vld[3],
                 &s_logit[tid*9 + d1], &s_logit[(tid+256)*9 + d1], c001);
    }

    // ============ direction 8 (rb) alone ============
    {
        const int d = 8;
        const int dy1 = (DY1 >> (2*d)) & 3;   // 2
        const int dx1 = (DX1 >> (2*d)) & 3;   // 2
        bool vA = (wA < WW - 4) && (h < HH - 4);
        bool vB = (wB < WW - 4) && (h < HH - 4);
        const int ca = (CA >> (2*d)) & 3, cb = (CB >> (2*d)) & 3;
        const float dAv = (ca == 0) ? fxa0 : ((ca == 1) ? fxa1 : fxa2);
        const float dBv = (cb == 0) ? fyb0 : ((cb == 1) ? fyb1 : fyb2);
        u64 dA2, dB2;
        PACK2(dA2, dAv, dAv);
        PACK2(dB2, dBv, dBv);
        const int row = (byl + dy1)*18 + (bxlA + dx1);
        const float* lpA = &s_lrproj[row*36];
        const float* lpB = &s_lrproj[(row + 8)*36];

        u64 accA[8], accB[8];
#pragma unroll
        for (int o = 0; o < 8; ++o) { accA[o] = 0ull; accB[o] = 0ull; }

#pragma unroll
        for (int q = 0; q < 16; ++q) {
            const u64 wa2 = *(const u64*)&wap[q*2];
            const u64 wb2 = *(const u64*)&wbp[q*2];
            u64 h0[2], h1v[2];
#pragma unroll
            for (int s = 0; s < 2; ++s) {
                const u64 l2 = *(const u64*)((s ? lpB : lpA) + q*2);
                u64 v;
                ADD2(v, (s ? hrpB[q] : hrpA[q]), l2);
                FMA2(v, dA2, wa2, v);
                FMA2(v, dB2, wb2, v);
                u64 m; float x0,x1,m0,m1;
                MUL2(m, v, c001);
                UNPK2(x0,x1,v); UNPK2(m0,m1,m);
                x0 = fmaxf(x0,m0); x1 = fmaxf(x1,m1);
                PACK2(h0[s],  x0, x0);
                PACK2(h1v[s], x1, x1);
            }
            {
                const ulonglong2* wr = (const ulonglong2*)&s_w1T[(2*q)*16];
                ulonglong2 r0 = wr[0], r1 = wr[1], r2 = wr[2], r3 = wr[3];
                FMA2(accA[0], r0.x, h0[0], accA[0]);
                FMA2(accA[1], r0.y, h0[0], accA[1]);
                FMA2(accA[2], r1.x, h0[0], accA[2]);
                FMA2(accA[3], r1.y, h0[0], accA[3]);
                FMA2(accA[4], r2.x, h0[0], accA[4]);
                FMA2(accA[5], r2.y, h0[0], accA[5]);
                FMA2(accA[6], r3.x, h0[0], accA[6]);
                FMA2(accA[7], r3.y, h0[0], accA[7]);
                FMA2(accB[0], r0.x, h0[1], accB[0]);
                FMA2(accB[1], r0.y, h0[1], accB[1]);
                FMA2(accB[2], r1.x, h0[1], accB[2]);
                FMA2(accB[3], r1.y, h0[1], accB[3]);
                FMA2(accB[4], r2.x, h0[1], accB[4]);
                FMA2(accB[5], r2.y, h0[1], accB[5]);
                FMA2(accB[6], r3.x, h0[1], accB[6]);
                FMA2(accB[7], r3.y, h0[1], accB[7]);
            }
            {
                const ulonglong2* wr = (const ulonglong2*)&s_w1T[(2*q+1)*16];
                ulonglong2 r0 = wr[0], r1 = wr[1], r2 = wr[2], r3 = wr[3];
                FMA2(accA[0], r0.x, h1v[0], accA[0]);
                FMA2(accA[1], r0.y, h1v[0], accA[1]);
                FMA2(accA[2], r1.x, h1v[0], accA[2]);
                FMA2(accA[3], r1.y, h1v[0], accA[3]);
                FMA2(accA[4], r2.x, h1v[0], accA[4]);
                FMA2(accA[5], r2.y, h1v[0], accA[5]);
                FMA2(accA[6], r3.x, h1v[0], accA[6]);
                FMA2(accA[7], r3.y, h1v[0], accA[7]);
                FMA2(accB[0], r0.x, h1v[1], accB[0]);
                FMA2(accB[1], r0.y, h1v[1], accB[1]);
                FMA2(accB[2], r1.x, h1v[1], accB[2]);
                FMA2(accB[3], r1.y, h1v[1], accB[3]);
                FMA2(accB[4], r2.x, h1v[1], accB[4]);
                FMA2(accB[5], r2.y, h1v[1], accB[5]);
                FMA2(accB[6], r3.x, h1v[1], accB[6]);
                FMA2(accB[7], r3.y, h1v[1], accB[7]);
            }
        }

        dir_tail(accA, accB, s_w2T, w3r, vA, vB,
                 &s_logit[tid*9 + 8], &s_logit[(tid+256)*9 + 8], c001);
    }

    // ---------------- softmax over the 9 directions, both pixels ----------------
#pragma unroll 1
    for (int pp = 0; pp < 2; ++pp) {
        const int pid = tid + pp*256;
        float lv[9];
#pragma unroll
        for (int d = 0; d < 9; ++d) lv[d] = s_logit[pid*9 + d];
        float m = lv[0];
#pragma unroll
        for (int d = 1; d < 9; ++d) m = fmaxf(m, lv[d]);
        float ssum = 0.f;
#pragma unroll
        for (int d = 0; d < 9; ++d) { float e = __expf(lv[d] - m); ssum += e; lv[d] = e; }
        const float inv = 1.0f / ssum;
        float* op = out + (size_t)b*9*HWs + (size_t)h*WW + wA + pp*32;
#pragma unroll
        for (int d = 0; d < 9; ++d) op[(size_t)d*HWs] = lv[d] * inv;
    }
}

extern "C" void kernel_launch(void* const* d_in, const int* in_sizes, int n_in,
                              void* d_out, int out_size) {
    const float* lr = (const float*)d_in[0];
    const float* hr = (const float*)d_in[1];
    // d_in[2], d_in[3] (lr_feature_r / hr_feature_r) are unused by the reference.
    const float* w0 = (const float*)d_in[4];
    const float* w1 = (const float*)d_in[5];
    const float* w2 = (const float*)d_in[6];
    const float* w3 = (const float*)d_in[7];
    dim3 grid(WW/64, HH/8, BB);
    erc_kernel<<<grid, 256>>>(lr, hr, w0, w1, w2, w3, (float*)d_out);
}